// round 7
// baseline (speedup 1.0000x reference)
#include <cuda_runtime.h>
#include <cuda_fp16.h>
#include <cstdint>

// Problem constants (match reference)
#define BATCH 4
#define CHANNELS 64
#define IMG 512
#define HW (IMG * IMG)
#define GRID_RES 64
#define CH_HALF 32

// 64 MB scratch: HALF the channels, NHWC (B, H, W, 32) in fp16.
// Half of L2 -> stays resident between its transpose pass and gather pass.
__device__ __half g_nhwc[(size_t)BATCH * HW * CH_HALF];

// ---------------------------------------------------------------------------
// Kernel 1: NCHW fp32 -> NHWC fp16 transpose of a 32-channel slice.
// Input reads streamed (__ldcs); scratch writes default (stay in L2 dirty).
// ---------------------------------------------------------------------------
__global__ void __launch_bounds__(256) transpose_half(const float* __restrict__ in,
                                                      int choff) {
    __shared__ float tile[32][65];

    int block = blockIdx.x;
    int b = block >> 12;                 // HW/64 = 4096 blocks per batch
    int hwbase = (block & 4095) << 6;    // *64

    const float* src = in + ((size_t)b * CHANNELS + choff) * HW;
    int tid = threadIdx.x;

    // Load: 32 channel rows x 64 hw, coalesced float4 along hw.
    int c0 = tid >> 4;            // 0..15
    int x4 = (tid & 15) << 2;     // 0..60
#pragma unroll
    for (int cc = c0; cc < 32; cc += 16) {
        float4 v = __ldcs((const float4*)(src + (size_t)cc * HW + hwbase + x4));
        tile[cc][x4 + 0] = v.x;
        tile[cc][x4 + 1] = v.y;
        tile[cc][x4 + 2] = v.z;
        tile[cc][x4 + 3] = v.w;
    }
    __syncthreads();

    // Store: 64 hw rows x 32 ch fp16 (64 B per pixel). 8 threads per pixel,
    // each writes 4 halves (uint2).
    int h0 = tid >> 3;            // 0..31
    int c4 = (tid & 7) << 2;      // 0..28
    __half* dst = g_nhwc + ((size_t)b * HW + hwbase) * CH_HALF;
#pragma unroll
    for (int h = h0; h < 64; h += 32) {
        __half2 lo = __floats2half2_rn(tile[c4 + 0][h], tile[c4 + 1][h]);
        __half2 hi = __floats2half2_rn(tile[c4 + 2][h], tile[c4 + 3][h]);
        uint2 v;
        v.x = *(const unsigned int*)&lo;
        v.y = *(const unsigned int*)&hi;
        *(uint2*)(dst + (size_t)h * CH_HALF + c4) = v;
    }
}

// ---------------------------------------------------------------------------
// Kernel 2: two-phase project + gather over one 32-channel slice.
// Phase 1: 1 thread = 1 point; projection; depth written in pass 0 only.
// Phase 2: 4 lanes = 1 point; corner = 64 B (uint4 per lane); output
//          128 B fp32 per point per pass, streamed.
// ---------------------------------------------------------------------------
template <bool FULL, int PASS>
__global__ void __launch_bounds__(256) project_gather(
    const int* __restrict__ coords,
    const float* __restrict__ Km,
    const float* __restrict__ Pm,
    float* __restrict__ out,
    int N)
{
    __shared__ float4 s_pt[256];    // {i_f, j_f, di, dj}
    __shared__ int    s_base[256];  // batch * HW * CH_HALF
    __shared__ float  sK[9];
    __shared__ float  sP[16];

    int tid = threadIdx.x;
    if (tid < 9)       sK[tid] = Km[tid];
    else if (tid < 25) sP[tid - 9] = Pm[tid - 9];
    __syncthreads();

    int base = blockIdx.x << 8;
    int p = base + tid;

    // ---- Phase 1: projection (one thread per point) ----
    if (FULL || p < N) {
        int4 cd = __ldcs((const int4*)(coords + (size_t)p * 4));

        const float scale = 2.0f / (float)(GRID_RES - 1);
        float wx = (float)cd.y * scale - 1.0f;
        float wy = (float)cd.z * scale - 1.0f;
        float wz = (float)cd.w * scale - 1.0f;

        float camx = sP[0]  * wx + sP[1]  * wy + sP[2]  * wz + sP[3];
        float camy = sP[4]  * wx + sP[5]  * wy + sP[6]  * wz + sP[7];
        float camz = sP[8]  * wx + sP[9]  * wy + sP[10] * wz + sP[11];
        float camw = sP[12] * wx + sP[13] * wy + sP[14] * wz + sP[15];
        float invw4 = 1.0f / camw;
        camx *= invw4; camy *= invw4; camz *= invw4;

        float u = sK[0] * camx + sK[1] * camy + sK[2] * camz;
        float v = sK[3] * camx + sK[4] * camy + sK[5] * camz;
        float w = sK[6] * camx + sK[7] * camy + sK[8] * camz;
        float invw = 1.0f / w;
        float x_real = u * invw;   // -> j (W)
        float y_real = v * invw;   // -> i (H)

        if (PASS == 0) {
            __stcs(out + (size_t)N * CHANNELS + p, camz);   // depth
        }

        float i_f = floorf(y_real);
        float j_f = floorf(x_real);
        s_pt[tid] = make_float4(i_f, j_f, y_real - i_f, x_real - j_f);
        s_base[tid] = cd.x * (HW * CH_HALF);
    }
    __syncthreads();

    // ---- Phase 2: gather (4 lanes per point, 4 points per lane-group) ----
    int lane = tid & 3;
    int grp  = tid >> 2;            // 64 point-groups
    int coff = lane << 3;           // 8 fp16 channels per lane
    int npts = FULL ? 256 : (N - base);

#pragma unroll
    for (int it = 0; it < 4; it++) {
        int pp = grp + (it << 6);
        if (!FULL && pp >= npts) break;

        float4 pt = s_pt[pp];
        int fb = s_base[pp];

        int ii = (int)pt.x;
        int jj = (int)pt.y;
        int i0 = min(max(ii, 0), IMG - 1);
        int i1 = min(max(ii + 1, 0), IMG - 1);
        int j0 = min(max(jj, 0), IMG - 1);
        int j1 = min(max(jj + 1, 0), IMG - 1);
        float di = pt.z;
        float dj = pt.w;

        const __half* bp = g_nhwc + fb + coff;
        int r0 = i0 << 14;    // i * IMG * CH_HALF
        int r1 = i1 << 14;
        int c0 = j0 << 5;     // j * CH_HALF
        int c1 = j1 << 5;

        uint4 a00 = *(const uint4*)(bp + r0 + c0);
        uint4 a01 = *(const uint4*)(bp + r0 + c1);
        uint4 a10 = *(const uint4*)(bp + r1 + c0);
        uint4 a11 = *(const uint4*)(bp + r1 + c1);

        float w00 = (1.0f - di) * (1.0f - dj);
        float w10 = di * (1.0f - dj);
        float w01 = (1.0f - di) * dj;
        float w11 = di * dj;

        const unsigned int* u00 = (const unsigned int*)&a00;
        const unsigned int* u01 = (const unsigned int*)&a01;
        const unsigned int* u10 = (const unsigned int*)&a10;
        const unsigned int* u11 = (const unsigned int*)&a11;

        float res[8];
#pragma unroll
        for (int k = 0; k < 4; k++) {
            float2 f00 = __half22float2(*(const __half2*)&u00[k]);
            float2 f01 = __half22float2(*(const __half2*)&u01[k]);
            float2 f10 = __half22float2(*(const __half2*)&u10[k]);
            float2 f11 = __half22float2(*(const __half2*)&u11[k]);
            res[2*k]   = w00 * f00.x + w10 * f10.x + w01 * f01.x + w11 * f11.x;
            res[2*k+1] = w00 * f00.y + w10 * f10.y + w01 * f01.y + w11 * f11.y;
        }

        float* op = out + ((size_t)(base + pp) << 6) + PASS * CH_HALF + coff;
        __stcs((float4*)op,     make_float4(res[0], res[1], res[2], res[3]));
        __stcs((float4*)op + 1, make_float4(res[4], res[5], res[6], res[7]));
    }
}

extern "C" void kernel_launch(void* const* d_in, const int* in_sizes, int n_in,
                              void* d_out, int out_size) {
    const int*   coords = (const int*)d_in[0];
    const float* feats  = (const float*)d_in[1];
    const float* Km     = (const float*)d_in[2];
    const float* Pm     = (const float*)d_in[3];
    float* out = (float*)d_out;

    int N = in_sizes[0] / 4;
    int tblocks = BATCH * (HW / 64);

    if ((N & 255) == 0) {
        int gblocks = N >> 8;
        transpose_half<<<tblocks, 256>>>(feats, 0);
        project_gather<true, 0><<<gblocks, 256>>>(coords, Km, Pm, out, N);
        transpose_half<<<tblocks, 256>>>(feats, CH_HALF);
        project_gather<true, 1><<<gblocks, 256>>>(coords, Km, Pm, out, N);
    } else {
        int gblocks = (N + 255) / 256;
        transpose_half<<<tblocks, 256>>>(feats, 0);
        project_gather<false, 0><<<gblocks, 256>>>(coords, Km, Pm, out, N);
        transpose_half<<<tblocks, 256>>>(feats, CH_HALF);
        project_gather<false, 1><<<gblocks, 256>>>(coords, Km, Pm, out, N);
    }
}